// round 4
// baseline (speedup 1.0000x reference)
#include <cuda_runtime.h>
#include <math.h>

#define NB   8
#define C    128
#define H    56
#define W    56
#define O    64
#define NC   2
#define KS   5
#define P    25
#define P2   50           // NC * P
#define HW   (H * W)      // 3136
#define PIX  (NB * HW)    // 25088

// Scratch (allocation-free rule: __device__ globals)
__device__ float g_V[P2 * C];       // folded weights V[p2][c], p2 = k*25 + p
__device__ float g_const[NC];       // per-class constant (bias@Wlin + blin)
__device__ float g_Y[NB * P2 * HW]; // projection output Y[n][p2][hw]

// ---------------------------------------------------------------------------
// Kernel 1: fold Wt (O,C,K,K) and Wlin (NC,O) into V (P2,C); fold bias/blin.
// ---------------------------------------------------------------------------
__global__ void prep_kernel(const float* __restrict__ Wt,
                            const float* __restrict__ bias,
                            const float* __restrict__ Wlin,
                            const float* __restrict__ blin) {
    int idx = blockIdx.x * blockDim.x + threadIdx.x;
    if (idx < P2 * C) {
        int p2 = idx / C;
        int c  = idx % C;
        int k  = p2 / P;
        int p  = p2 % P;
        float s = 0.f;
        #pragma unroll
        for (int o = 0; o < O; o++) {
            s += Wlin[k * O + o] * Wt[(o * C + c) * P + p];
        }
        g_V[p2 * C + c] = s;
    }
    if (idx < NC) {
        float s = blin[idx];
        #pragma unroll
        for (int o = 0; o < O; o++) s += bias[o] * Wlin[idx * O + o];
        g_const[idx] = s;
    }
}

// ---------------------------------------------------------------------------
// Kernel 2: pointwise projection Y[n,p2,hw] = sum_c V[p2,c] * x[n,c,hw].
// One thread per pixel, 50 accumulators; V staged in shared, read as float4.
// ---------------------------------------------------------------------------
__global__ void __launch_bounds__(128) proj_kernel(const float* __restrict__ x) {
    __shared__ float4 sV[P2 * C / 4];   // 25.6 KB
    for (int i = threadIdx.x; i < P2 * C / 4; i += blockDim.x)
        sV[i] = reinterpret_cast<const float4*>(g_V)[i];
    __syncthreads();

    int pix = blockIdx.x * 128 + threadIdx.x;  // grid chosen so pix < PIX always
    int n  = pix / HW;
    int hw = pix % HW;
    const float* xb = x + (size_t)n * C * HW + hw;

    float acc[P2];
    #pragma unroll
    for (int p = 0; p < P2; p++) acc[p] = 0.f;

    #pragma unroll 2
    for (int c4 = 0; c4 < C / 4; c4++) {
        float x0 = xb[(c4 * 4 + 0) * HW];
        float x1 = xb[(c4 * 4 + 1) * HW];
        float x2 = xb[(c4 * 4 + 2) * HW];
        float x3 = xb[(c4 * 4 + 3) * HW];
        #pragma unroll
        for (int p = 0; p < P2; p++) {
            float4 wv = sV[p * (C / 4) + c4];
            acc[p] = fmaf(wv.x, x0, acc[p]);
            acc[p] = fmaf(wv.y, x1, acc[p]);
            acc[p] = fmaf(wv.z, x2, acc[p]);
            acc[p] = fmaf(wv.w, x3, acc[p]);
        }
    }

    float* yb = g_Y + (size_t)n * P2 * HW + hw;
    #pragma unroll
    for (int p = 0; p < P2; p++) yb[p * HW] = acc[p];
}

// ---------------------------------------------------------------------------
// Kernel 3: 5x5 spatial gather of Y + drift/exp epilogue.
// One thread per pixel, computes both classes.
// ---------------------------------------------------------------------------
__global__ void __launch_bounds__(256) final_kernel(float* __restrict__ out) {
    int pix = blockIdx.x * blockDim.x + threadIdx.x;
    if (pix >= PIX) return;
    int n  = pix / HW;
    int hw = pix % HW;
    int h  = hw / W;
    int w  = hw % W;

    const float* yb = g_Y + (size_t)n * P2 * HW;
    float c0 = g_const[0], c1 = g_const[1];

    float sum0 = 0.f, sum1 = 0.f;
    float as0 = 0.f, as1 = 0.f;
    float ys0 = 0.f, ys1 = 0.f;
    float xs0 = 0.f, xs1 = 0.f;

    #pragma unroll
    for (int i = 0; i < KS; i++) {
        int hh = h + i - 2;
        bool hin = (hh >= 0) && (hh < H);
        #pragma unroll
        for (int j = 0; j < KS; j++) {
            int ww = w + j - 2;
            bool in = hin && (ww >= 0) && (ww < W);
            int p = i * KS + j;
            float v0 = 0.f, v1 = 0.f;
            if (in) {
                int idx = hh * W + ww;
                v0 = yb[p * HW + idx];
                v1 = yb[(P + p) * HW + idx];
            }
            float m0 = v0 + c0, m1 = v1 + c1;
            float a0 = fabsf(m0), a1 = fabsf(m1);
            float yo = (float)(i - 2), xo = (float)(j - 2);
            sum0 += m0;      sum1 += m1;
            as0  += a0;      as1  += a1;
            ys0  = fmaf(a0, yo, ys0);  ys1 = fmaf(a1, yo, ys1);
            xs0  = fmaf(a0, xo, xs0);  xs1 = fmaf(a1, xo, xs1);
        }
    }

    float yd0 = ys0 / as0, xd0 = xs0 / as0;
    float yd1 = ys1 / as1, xd1 = xs1 / as1;
    float d0 = sqrtf(fmaf(xd0, xd0, yd0 * yd0));
    float d1 = sqrtf(fmaf(xd1, xd1, yd1 * yd1));
    out[pix * 2 + 0] = sum0 * expf(-0.5f * d0);
    out[pix * 2 + 1] = sum1 * expf(-0.5f * d1);
}

// ---------------------------------------------------------------------------
extern "C" void kernel_launch(void* const* d_in, const int* in_sizes, int n_in,
                              void* d_out, int out_size) {
    const float* x    = (const float*)d_in[0];  // (8,128,56,56)
    const float* Wt   = (const float*)d_in[1];  // (64,128,5,5)
    const float* bias = (const float*)d_in[2];  // (64,)
    const float* Wlin = (const float*)d_in[3];  // (2,64)
    const float* blin = (const float*)d_in[4];  // (2,)
    float* out = (float*)d_out;                 // (8,56,56,2)

    prep_kernel<<<(P2 * C + 127) / 128, 128>>>(Wt, bias, Wlin, blin);
    proj_kernel<<<PIX / 128, 128>>>(x);         // 196 blocks, exact
    final_kernel<<<(PIX + 255) / 256, 256>>>(out);
}